// round 2
// baseline (speedup 1.0000x reference)
#include <cuda_runtime.h>
#include <math.h>
#include <float.h>

// Problem constants
#define BB     4096
#define NNODE  50
#define DIM    64
#define KASSIGN 10
#define NCAND  5
#define MAXLEN 512

// Device scratch (no allocations allowed)
__device__ float g_PEW[MAXLEN * DIM];     // (pe @ W_PE) table
__device__ float g_part[BB * 4];          // per-batch loss partials

// ---------------------------------------------------------------------------
// Kernel 0: PEW[t][c] = sum_k pe[t][k] * W_PE[k][c]
// ---------------------------------------------------------------------------
__global__ void pew_kernel(const float* __restrict__ W_PE) {
    __shared__ float pe[DIM];
    int t = blockIdx.x;
    int tid = threadIdx.x;
    if (tid < 32) {
        float div = expf(-(2.0f * tid) * (logf(10000.0f) / 64.0f));
        float ang = (float)t * div;
        pe[2 * tid]     = sinf(ang);
        pe[2 * tid + 1] = cosf(ang);
    }
    __syncthreads();
    float s = 0.f;
#pragma unroll 8
    for (int k = 0; k < DIM; k++) s += pe[k] * W_PE[k * DIM + tid];
    g_PEW[t * DIM + tid] = s;
}

// ---------------------------------------------------------------------------
// 64x64 register-tiled GEMM: C[n][c] = sum_k A[n][k]*B[k][c]
// Thread map: tc = tid&31 (cols tc, tc+32), tn = tid>>5 (rows tn+8i, i<8).
// A loads are warp-uniform (broadcast), B loads are conflict-free.
// ---------------------------------------------------------------------------
template <int KLEN>
__device__ __forceinline__ void gemm_tile(const float* __restrict__ A,
                                          const float* __restrict__ B,
                                          float* __restrict__ C,
                                          int tn, int tc) {
    float acc[8][2];
#pragma unroll
    for (int i = 0; i < 8; i++) { acc[i][0] = 0.f; acc[i][1] = 0.f; }
#pragma unroll 2
    for (int k = 0; k < KLEN; k++) {
        float b0 = B[k * 64 + tc];
        float b1 = B[k * 64 + tc + 32];
#pragma unroll
        for (int i = 0; i < 8; i++) {
            float a = A[(tn + 8 * i) * 64 + k];
            acc[i][0] = fmaf(a, b0, acc[i][0]);
            acc[i][1] = fmaf(a, b1, acc[i][1]);
        }
    }
#pragma unroll
    for (int i = 0; i < 8; i++) {
        C[(tn + 8 * i) * 64 + tc]      = acc[i][0];
        C[(tn + 8 * i) * 64 + tc + 32] = acc[i][1];
    }
}

__device__ __forceinline__ float warp_sum(float v) {
#pragma unroll
    for (int o = 16; o; o >>= 1) v += __shfl_xor_sync(0xffffffffu, v, o);
    return v;
}
__device__ __forceinline__ float warp_max(float v) {
#pragma unroll
    for (int o = 16; o; o >>= 1) v = fmaxf(v, __shfl_xor_sync(0xffffffffu, v, o));
    return v;
}

// ---------------------------------------------------------------------------
// Kernel A: full per-batch pipeline, one CTA per batch element, 256 threads.
// ---------------------------------------------------------------------------
__global__ __launch_bounds__(256, 2) void main_kernel(
    const float* __restrict__ emb,
    const float* __restrict__ W_pred,
    const float* __restrict__ W_gat,
    const float* __restrict__ a_src,
    const float* __restrict__ a_dst,
    const float* __restrict__ W_o,
    const float* __restrict__ W_assign,
    const float* __restrict__ adj,
    const int*   __restrict__ history,
    const int*   __restrict__ timestp,
    const int*   __restrict__ pos_id,
    const int*   __restrict__ neg_id,
    const int*   __restrict__ stp)
{
    extern __shared__ float sm[];
    float* x    = sm;                 // 4096  x (padded 64x64, rows>=50 zero)
    float* Wh   = sm + 4096;          // 4096
    float* attn = sm + 8192;          // 4096  (later aliased as xI)
    float* P    = sm + 12288;         // 4096  (later aliased as xIT, stride 65, spills 64 into Wb)
    float* Wb   = sm + 16384;         // 4096  W_gat[h] / W_o slice
    float* xp   = sm + 20480;         // 640   x_parent 10x64
    float* cand = sm + 21120;         // 320
    float* ssm  = sm + 21440;         // 512   s (50x10)
    float* esd  = sm + 21952;         // 128   es[64], ed[64]
    float* uIm  = sm + 22080;         // 64    user_I
    float* uFm  = sm + 22144;         // 64    user_F
    float* aggw = sm + 22208;         // 320   u_I attn weights (5 x 64)
    float* aggwF= sm + 22528;         // 320   u_F attn weights
    float* uFo  = sm + 22848;         // 320
    float* uIo  = sm + 23168;         // 320
    float* uo   = sm + 23488;         // 320
    float* av   = sm + 23808;         // 128   a_src[64], a_dst[64]
    float* red  = sm + 23936;         // 256
    float* sc5  = sm + 24192;         // 32    scores/sI/sF/norms
    float* xpT  = sm + 24224;         // 768   xp transposed, stride 12
    int*   ism  = (int*)(sm + 24992); // 128   indices
    // total 25120 floats = 100480 bytes

    const int tid = threadIdx.x;
    const int b   = blockIdx.x;
    const int lane = tid & 31;
    const int w    = tid >> 5;
    const int tc = lane;
    const int tn = w;

    // ---------------- Stage 0: indices, x, cand, reg partial ----------------
    if (tid < 50) {
        ism[tid]      = history[b * 50 + tid];
        ism[50 + tid] = timestp[b * 50 + tid];
    } else if (tid < 54) {
        ism[100 + (tid - 50)] = neg_id[b * 4 + (tid - 50)];
    } else if (tid == 54) {
        ism[104] = pos_id[b];
    } else if (tid == 55) {
        ism[105] = stp[b];
    }
    __syncthreads();

    for (int i = 50 * 64 + tid; i < 64 * 64; i += 256) { x[i] = 0.f; attn[i] = 0.f; }

    float regp = 0.f;
    for (int i = tid; i < 50 * 64; i += 256) {
        int n = i >> 6, d = i & 63;
        int h = ism[n];
        float e = emb[h * 64 + d];
        regp += e * e;
        x[i] = (h > 0) ? (e + g_PEW[ism[50 + n] * 64 + d]) : 0.f;
    }
    for (int i = tid; i < 5 * 64; i += 256) {
        int c = i >> 6, d = i & 63;
        int id = (c == 0) ? ism[104] : ism[100 + c - 1];
        float e = emb[id * 64 + d];
        regp += e * e;
        cand[i] = e + g_PEW[ism[105] * 64 + d];
    }
    __syncthreads();

    // ---------------- s = softmax(x @ W_assign) + entropy -------------------
    for (int i = tid; i < 500; i += 256) {
        int n = i / 10, k = i - n * 10;
        float acc = 0.f;
#pragma unroll 4
        for (int d = 0; d < 64; d++) acc += x[n * 64 + d] * W_assign[d * 10 + k];
        ssm[i] = acc;
    }
    __syncthreads();
    float entp = 0.f;
    if (tid < 50) {
        float mx = -FLT_MAX;
        float e[10];
#pragma unroll
        for (int k = 0; k < 10; k++) mx = fmaxf(mx, ssm[tid * 10 + k]);
        float ssum = 0.f;
#pragma unroll
        for (int k = 0; k < 10; k++) { e[k] = expf(ssm[tid * 10 + k] - mx); ssum += e[k]; }
        float inv = 1.f / ssum;
#pragma unroll
        for (int k = 0; k < 10; k++) {
            float sv = e[k] * inv;
            ssm[tid * 10 + k] = sv;
            entp -= sv * logf(fmaxf(sv, 1e-30f));
        }
    }
    __syncthreads();

    // ---------------- x_parent, xpT, user_F ---------------------------------
    for (int i = tid; i < 640; i += 256) {
        int kk = i >> 6, d = i & 63;
        float acc = 0.f;
        for (int n = 0; n < 50; n++) acc += ssm[n * 10 + kk] * x[n * 64 + d];
        xp[i] = acc;
        xpT[d * 12 + kk] = acc;
    }
    __syncthreads();
    if (tid < 64) {
        float s = 0.f;
#pragma unroll
        for (int kk = 0; kk < 10; kk++) s += xp[kk * 64 + tid];
        uFm[tid] = s * 0.1f;
    }

    // ---------------- GAT: 4 heads ------------------------------------------
    float gacc[8][2];
#pragma unroll
    for (int i = 0; i < 8; i++) { gacc[i][0] = 0.f; gacc[i][1] = 0.f; }

    const float* adjb = adj + (size_t)b * 2500;

    for (int h = 0; h < 4; h++) {
        for (int i = tid; i < 4096; i += 256) Wb[i] = W_gat[h * 4096 + i];
        if (tid < 64)       av[tid] = a_src[h * 64 + tid];
        else if (tid < 128) av[tid] = a_dst[h * 64 + (tid - 64)];
        __syncthreads();

        gemm_tile<64>(x, Wb, Wh, tn, tc);          // Wh = x @ W_gat[h]
        __syncthreads();

        // es/ed: warp-per-row reductions
        for (int r = w; r < 50; r += 8) {
            float v  = Wh[r * 64 + lane] * av[lane]      + Wh[r * 64 + lane + 32] * av[lane + 32];
            float u2 = Wh[r * 64 + lane] * av[64 + lane] + Wh[r * 64 + lane + 32] * av[96 + lane];
            v  = warp_sum(v);
            u2 = warp_sum(u2);
            if (lane == 0) { esd[r] = v; esd[64 + r] = u2; }
        }
        __syncthreads();

        // masked leaky-relu softmax rows
        for (int r = w; r < 50; r += 8) {
            float esr = esd[r];
            float v1 = esr + esd[64 + lane];
            v1 = v1 > 0.f ? v1 : 0.2f * v1;
            v1 = (adjb[r * 50 + lane] > 0.f) ? v1 : -1e9f;
            float v2 = -FLT_MAX;
            if (lane < 18) {
                float t2 = esr + esd[64 + lane + 32];
                t2 = t2 > 0.f ? t2 : 0.2f * t2;
                v2 = (adjb[r * 50 + lane + 32] > 0.f) ? t2 : -1e9f;
            }
            float mx = warp_max(fmaxf(v1, v2));
            float e1 = expf(v1 - mx);
            float e2 = (lane < 18) ? expf(v2 - mx) : 0.f;
            float ssum = warp_sum(e1 + e2);
            float inv = 1.f / ssum;
            attn[r * 64 + lane] = e1 * inv;
            if (lane < 18) attn[r * 64 + lane + 32] = e2 * inv;
        }
        __syncthreads();

        gemm_tile<50>(attn, Wh, P, tn, tc);        // P = attn @ Wh
        __syncthreads();

        for (int i = tid; i < 4096; i += 256) Wb[i] = W_o[h * 4096 + i];
        __syncthreads();

        // gacc += P @ W_o[h]
#pragma unroll 2
        for (int k = 0; k < 64; k++) {
            float b0 = Wb[k * 64 + tc];
            float b1 = Wb[k * 64 + tc + 32];
#pragma unroll
            for (int i = 0; i < 8; i++) {
                float a = P[(tn + 8 * i) * 64 + k];
                gacc[i][0] = fmaf(a, b0, gacc[i][0]);
                gacc[i][1] = fmaf(a, b1, gacc[i][1]);
            }
        }
        __syncthreads();
    }

    // xI = elu(gacc), row-major into attn buffer; transposed into P buffer
    float* xI  = attn;
    float* xIT = P;  // stride 65, 64*65=4160 floats (spills 64 into dead Wb)
#pragma unroll
    for (int i = 0; i < 8; i++) {
        int n = tn + 8 * i;
        float v0 = gacc[i][0], v1 = gacc[i][1];
        v0 = v0 > 0.f ? v0 : expm1f(v0);
        v1 = v1 > 0.f ? v1 : expm1f(v1);
        xI[n * 64 + tc]        = v0;
        xI[n * 64 + tc + 32]   = v1;
        xIT[tc * 65 + n]       = v0;
        xIT[(tc + 32) * 65 + n] = v1;
    }
    __syncthreads();

    // user_I
    if (tid < 64) {
        float s = 0.f;
        for (int n = 0; n < 50; n++) s += xI[n * 64 + tid];
        uIm[tid] = s * 0.02f;
    }
    __syncthreads();

    // ---------------- aggregates u_I (warps 0-4), u_F (warps 5-7) ----------
    if (w < 5) {
        int c = w;
        float d1 = 0.f, d2 = 0.f;
        for (int d = 0; d < 64; d++) {
            float cv = cand[c * 64 + d];
            d1 += xIT[d * 65 + lane] * cv;
            d2 += xIT[d * 65 + lane + 32] * cv;
        }
        float v1 = d1;
        float v2 = (lane < 18) ? d2 : -FLT_MAX;
        float mx = warp_max(fmaxf(v1, v2));
        float e1 = expf(v1 - mx);
        float e2 = (lane < 18) ? expf(v2 - mx) : 0.f;
        float inv = 1.f / warp_sum(e1 + e2);
        aggw[c * 64 + lane] = e1 * inv;
        if (lane < 18) aggw[c * 64 + lane + 32] = e2 * inv;
        __syncwarp();
        float o1 = 0.f, o2 = 0.f;
        for (int n = 0; n < 50; n++) {
            float wn = aggw[c * 64 + n];
            o1 += wn * xI[n * 64 + lane];
            o2 += wn * xI[n * 64 + lane + 32];
        }
        uIo[c * 64 + lane]      = o1;
        uIo[c * 64 + lane + 32] = o2;
    } else {
        for (int c = w - 5; c < 5; c += 3) {
            float d1 = 0.f;
            if (lane < 10) {
                for (int d = 0; d < 64; d++) d1 += xpT[d * 12 + lane] * cand[c * 64 + d];
            }
            float v1 = (lane < 10) ? d1 : -FLT_MAX;
            float mx = warp_max(v1);
            float e1 = (lane < 10) ? expf(v1 - mx) : 0.f;
            float inv = 1.f / warp_sum(e1);
            if (lane < 10) aggwF[c * 64 + lane] = e1 * inv;
            __syncwarp();
            float o1 = 0.f, o2 = 0.f;
#pragma unroll
            for (int n = 0; n < 10; n++) {
                float wn = aggwF[c * 64 + n];
                o1 += wn * xp[n * 64 + lane];
                o2 += wn * xp[n * 64 + lane + 32];
            }
            uFo[c * 64 + lane]      = o1;
            uFo[c * 64 + lane + 32] = o2;
            __syncwarp();
        }
    }
    __syncthreads();

    // ---------------- u = concat(uF,uI) @ W_pred ----------------------------
    for (int i = tid; i < 320; i += 256) {
        int c = i >> 6, d = i & 63;
        float acc = 0.f;
#pragma unroll 4
        for (int k = 0; k < 64; k++) acc += uFo[c * 64 + k] * W_pred[k * 64 + d];
#pragma unroll 4
        for (int k = 0; k < 64; k++) acc += uIo[c * 64 + k] * W_pred[(64 + k) * 64 + d];
        uo[i] = acc;
    }
    __syncthreads();

    // ---------------- scores, sI, sF, norms ---------------------------------
    if (tid < 5) {
        float a = 0.f;
        for (int d = 0; d < 64; d++) a += uo[tid * 64 + d] * cand[tid * 64 + d];
        sc5[tid] = a;
    } else if (tid >= 8 && tid < 13) {
        int c = tid - 8; float a = 0.f;
        for (int d = 0; d < 64; d++) a += cand[c * 64 + d] * uIm[d];
        sc5[5 + c] = a;
    } else if (tid >= 16 && tid < 21) {
        int c = tid - 16; float a = 0.f;
        for (int d = 0; d < 64; d++) a += cand[c * 64 + d] * uFm[d];
        sc5[10 + c] = a;
    } else if (tid >= 24 && tid < 29) {
        int c = tid - 24; float a = 0.f;
        for (int d = 0; d < 64; d++) a += cand[c * 64 + d] * cand[c * 64 + d];
        sc5[16 + c] = sqrtf(a);
    } else if (tid == 29) {
        float a = 0.f;
        for (int d = 0; d < 64; d++) a += uIm[d] * uIm[d];
        sc5[21] = sqrtf(a);
    } else if (tid == 30) {
        float a = 0.f;
        for (int d = 0; d < 64; d++) a += uFm[d] * uFm[d];
        sc5[22] = sqrtf(a);
    }
    __syncthreads();

    // ---------------- thread 0: loss, top-k, ssl ----------------------------
    if (tid == 0) {
        float p = sc5[0];
        float l1 = 0.f;
        for (int c = 1; c < 5; c++) {
            float z = sc5[c] - p;
            l1 += fmaxf(z, 0.f) + log1pf(expf(-fabsf(z)));
        }
        float vI[5], vF[5]; int iI[5], iF[5];
        for (int j = 0; j < 5; j++) { vI[j] = sc5[5 + j]; iI[j] = j; vF[j] = sc5[10 + j]; iF[j] = j; }
        for (int a2 = 0; a2 < 4; a2++) {
            int m = a2;
            for (int j = a2 + 1; j < 5; j++) if (vI[j] > vI[m]) m = j;
            float tv = vI[a2]; vI[a2] = vI[m]; vI[m] = tv;
            int ti = iI[a2]; iI[a2] = iI[m]; iI[m] = ti;
            m = a2;
            for (int j = a2 + 1; j < 5; j++) if (vF[j] > vF[m]) m = j;
            tv = vF[a2]; vF[a2] = vF[m]; vF[m] = tv;
            ti = iF[a2]; iF[a2] = iF[m]; iF[m] = ti;
        }
        float nuI = sc5[21], nuF = sc5[22];
        float psI = expf(2.f * sc5[5 + iF[0]] / (sc5[16 + iF[0]] * nuI))
                  + expf(2.f * sc5[5 + iF[1]] / (sc5[16 + iF[1]] * nuI));
        float nsI = expf(2.f * sc5[5 + iF[2]] / (sc5[16 + iF[2]] * nuI))
                  + expf(2.f * sc5[5 + iF[3]] / (sc5[16 + iF[3]] * nuI));
        float termI = logf(psI + nsI) - logf(psI);
        float psF = expf(2.f * sc5[10 + iI[0]] / (sc5[16 + iI[0]] * nuF))
                  + expf(2.f * sc5[10 + iI[1]] / (sc5[16 + iI[1]] * nuF));
        float nsF = expf(2.f * sc5[10 + iI[2]] / (sc5[16 + iI[2]] * nuF))
                  + expf(2.f * sc5[10 + iI[3]] / (sc5[16 + iI[3]] * nuF));
        float termF = logf(psF + nsF) - logf(psF);
        g_part[b * 4 + 0] = l1;
        g_part[b * 4 + 3] = termI + termF;
    }

    // ---------------- block reductions: reg, entropy ------------------------
    red[tid] = regp;
    __syncthreads();
    for (int s2 = 128; s2 > 0; s2 >>= 1) {
        if (tid < s2) red[tid] += red[tid + s2];
        __syncthreads();
    }
    if (tid == 0) g_part[b * 4 + 1] = red[0];
    __syncthreads();
    red[tid] = (tid < 50) ? entp : 0.f;
    __syncthreads();
    for (int s2 = 128; s2 > 0; s2 >>= 1) {
        if (tid < s2) red[tid] += red[tid + s2];
        __syncthreads();
    }
    if (tid == 0) g_part[b * 4 + 2] = red[0];
}

// ---------------------------------------------------------------------------
// Kernel B: deterministic final reduction + weight L2 terms
// ---------------------------------------------------------------------------
__global__ void reduce_kernel(const float* __restrict__ W_pred,
                              const float* __restrict__ W_PE,
                              float* __restrict__ out) {
    __shared__ double rs[256];
    int tid = threadIdx.x;
    double a0 = 0, a1 = 0, a2 = 0, a3 = 0, wv = 0;
    for (int i = tid; i < BB; i += 256) {
        const float* p = &g_part[i * 4];
        a0 += p[0]; a1 += p[1]; a2 += p[2]; a3 += p[3];
    }
    for (int i = tid; i < 8192; i += 256) { double v = W_pred[i]; wv += v * v; }
    for (int i = tid; i < 4096; i += 256) { double v = W_PE[i];   wv += v * v; }
    double vals[5] = {a0, a1, a2, a3, wv};
    double res[5];
    for (int j = 0; j < 5; j++) {
        rs[tid] = vals[j];
        __syncthreads();
        for (int s = 128; s > 0; s >>= 1) {
            if (tid < s) rs[tid] += rs[tid + s];
            __syncthreads();
        }
        res[j] = rs[0];
        __syncthreads();
    }
    if (tid == 0) {
        out[0] = (float)(res[0] / (4096.0 * 4.0));
        out[1] = (float)(res[1] / 4096.0 + res[4]);
        out[2] = (float)(res[2] / (50.0 * 4096.0));
        out[3] = (float)(res[3] / 4096.0);
    }
}

// ---------------------------------------------------------------------------
extern "C" void kernel_launch(void* const* d_in, const int* in_sizes, int n_in,
                              void* d_out, int out_size) {
    const float* emb      = (const float*)d_in[0];
    const float* W_PE     = (const float*)d_in[1];
    const float* W_pred   = (const float*)d_in[2];
    const float* W_gat    = (const float*)d_in[3];
    const float* a_src    = (const float*)d_in[4];
    const float* a_dst    = (const float*)d_in[5];
    const float* W_o      = (const float*)d_in[6];
    const float* W_assign = (const float*)d_in[7];
    const float* adj      = (const float*)d_in[8];
    const int*   history  = (const int*)d_in[9];
    const int*   timestp  = (const int*)d_in[10];
    const int*   pos_id   = (const int*)d_in[11];
    const int*   neg_id   = (const int*)d_in[12];
    const int*   stp      = (const int*)d_in[13];
    float* out = (float*)d_out;

    const int smem_bytes = 25120 * 4;  // 100480
    cudaFuncSetAttribute(main_kernel, cudaFuncAttributeMaxDynamicSharedMemorySize, smem_bytes);

    pew_kernel<<<MAXLEN, 64>>>(W_PE);
    main_kernel<<<BB, 256, smem_bytes>>>(emb, W_pred, W_gat, a_src, a_dst, W_o,
                                         W_assign, adj, history, timestp,
                                         pos_id, neg_id, stp);
    reduce_kernel<<<1, 256>>>(W_pred, W_PE, out);
}

// round 3
// speedup vs baseline: 1.0826x; 1.0826x over previous
#include <cuda_runtime.h>
#include <math.h>
#include <float.h>

// Problem constants
#define BB     4096
#define NNODE  50
#define DIM    64
#define MAXLEN 512

__device__ float g_PEW[MAXLEN * DIM];
__device__ float g_part[BB * 4];

// ---------------------------------------------------------------------------
__global__ void pew_kernel(const float* __restrict__ W_PE) {
    __shared__ float pe[DIM];
    int t = blockIdx.x;
    int tid = threadIdx.x;
    if (tid < 32) {
        float div = expf(-(2.0f * tid) * (logf(10000.0f) / 64.0f));
        float ang = (float)t * div;
        pe[2 * tid]     = sinf(ang);
        pe[2 * tid + 1] = cosf(ang);
    }
    __syncthreads();
    float s = 0.f;
#pragma unroll 8
    for (int k = 0; k < DIM; k++) s += pe[k] * W_PE[k * DIM + tid];
    g_PEW[t * DIM + tid] = s;
}

// ---------------------------------------------------------------------------
// Packed f32x2 helpers
// ---------------------------------------------------------------------------
__device__ __forceinline__ void ffma2(unsigned long long& acc,
                                      unsigned long long a,
                                      unsigned long long b) {
    asm("fma.rn.f32x2 %0, %1, %2, %0;" : "+l"(acc) : "l"(a), "l"(b));
}
__device__ __forceinline__ unsigned long long ld64(const float* p) {
    return *reinterpret_cast<const unsigned long long*>(p);
}
__device__ __forceinline__ float hsum2(unsigned long long v) {
    return __uint_as_float((unsigned)(v)) + __uint_as_float((unsigned)(v >> 32));
}

__device__ __forceinline__ float warp_sum(float v) {
#pragma unroll
    for (int o = 16; o; o >>= 1) v += __shfl_xor_sync(0xffffffffu, v, o);
    return v;
}
__device__ __forceinline__ float warp_max(float v) {
#pragma unroll
    for (int o = 16; o; o >>= 1) v = fmaxf(v, __shfl_xor_sync(0xffffffffu, v, o));
    return v;
}

// ---------------------------------------------------------------------------
// Main kernel: one CTA per batch element, 256 threads, packed-f32x2 GEMMs.
// GEMM convention: A row-major stride 64; Bt = B transposed, stride 66;
// per-thread tile rows tn+8i (i<8), cols (tc, tc+32); accumulators hold
// (even-k, odd-k) partial pairs, horizontal-summed at epilogue.
// ---------------------------------------------------------------------------
__global__ __launch_bounds__(256, 2) void main_kernel(
    const float* __restrict__ emb,
    const float* __restrict__ W_pred,
    const float* __restrict__ W_gat,
    const float* __restrict__ a_src,
    const float* __restrict__ a_dst,
    const float* __restrict__ W_o,
    const float* __restrict__ W_assign,
    const float* __restrict__ adj,
    const int*   __restrict__ history,
    const int*   __restrict__ timestp,
    const int*   __restrict__ pos_id,
    const int*   __restrict__ neg_id,
    const int*   __restrict__ stp)
{
    extern __shared__ float sm[];
    float* x    = sm;                  // 4096
    float* WhT  = sm + 4096;           // 4224 (64 cols x stride 66)
    float* attn = sm + 8320;           // 4096 (later aliased as xI)
    float* P    = sm + 12416;          // 4096 (later aliased as xIT stride 65, spills into Wb)
    float* Wb   = sm + 16512;          // 4224 transposed weight slice
    float* xp   = sm + 20736;          // 640
    float* cand = sm + 21376;          // 320
    float* ssm  = sm + 21696;          // 512
    float* esd  = sm + 22208;          // 128
    float* uIm  = sm + 22336;          // 64
    float* uFm  = sm + 22400;          // 64
    float* aggw = sm + 22464;          // 320
    float* aggwF= sm + 22784;          // 320
    float* uFo  = sm + 23104;          // 320
    float* uIo  = sm + 23424;          // 320
    float* uo   = sm + 23744;          // 320
    float* av   = sm + 24064;          // 128
    float* red  = sm + 24192;          // 256
    float* sc5  = sm + 24448;          // 32
    float* xpT  = sm + 24480;          // 768
    int*   ism  = (int*)(sm + 25248);  // 128
    // total 25376 floats = 101504 bytes

    const int tid = threadIdx.x;
    const int b   = blockIdx.x;
    const int lane = tid & 31;
    const int w    = tid >> 5;
    const int tc = lane;
    const int tn = w;

    // ---------------- Stage 0 ----------------
    if (tid < 50) {
        ism[tid]      = history[b * 50 + tid];
        ism[50 + tid] = timestp[b * 50 + tid];
    } else if (tid < 54) {
        ism[100 + (tid - 50)] = neg_id[b * 4 + (tid - 50)];
    } else if (tid == 54) {
        ism[104] = pos_id[b];
    } else if (tid == 55) {
        ism[105] = stp[b];
    }
    __syncthreads();

    for (int i = 50 * 64 + tid; i < 64 * 64; i += 256) { x[i] = 0.f; attn[i] = 0.f; }

    float regp = 0.f;
    for (int i = tid; i < 50 * 64; i += 256) {
        int n = i >> 6, d = i & 63;
        int h = ism[n];
        float e = emb[h * 64 + d];
        regp += e * e;
        x[i] = (h > 0) ? (e + g_PEW[ism[50 + n] * 64 + d]) : 0.f;
    }
    for (int i = tid; i < 5 * 64; i += 256) {
        int c = i >> 6, d = i & 63;
        int id = (c == 0) ? ism[104] : ism[100 + c - 1];
        float e = emb[id * 64 + d];
        regp += e * e;
        cand[i] = e + g_PEW[ism[105] * 64 + d];
    }
    __syncthreads();

    // ---------------- assign softmax + entropy ----------------
    for (int i = tid; i < 500; i += 256) {
        int n = i / 10, k = i - n * 10;
        float acc = 0.f;
#pragma unroll 4
        for (int d = 0; d < 64; d++) acc += x[n * 64 + d] * W_assign[d * 10 + k];
        ssm[i] = acc;
    }
    __syncthreads();
    float entp = 0.f;
    if (tid < 50) {
        float mx = -FLT_MAX;
        float e[10];
#pragma unroll
        for (int k = 0; k < 10; k++) mx = fmaxf(mx, ssm[tid * 10 + k]);
        float ssum = 0.f;
#pragma unroll
        for (int k = 0; k < 10; k++) { e[k] = expf(ssm[tid * 10 + k] - mx); ssum += e[k]; }
        float inv = 1.f / ssum;
#pragma unroll
        for (int k = 0; k < 10; k++) {
            float sv = e[k] * inv;
            ssm[tid * 10 + k] = sv;
            entp -= sv * logf(fmaxf(sv, 1e-30f));
        }
    }
    __syncthreads();

    // ---------------- x_parent, xpT, user_F ----------------
    for (int i = tid; i < 640; i += 256) {
        int kk = i >> 6, d = i & 63;
        float acc = 0.f;
        for (int n = 0; n < 50; n++) acc += ssm[n * 10 + kk] * x[n * 64 + d];
        xp[i] = acc;
        xpT[d * 12 + kk] = acc;
    }
    __syncthreads();
    if (tid < 64) {
        float s = 0.f;
#pragma unroll
        for (int kk = 0; kk < 10; kk++) s += xp[kk * 64 + tid];
        uFm[tid] = s * 0.1f;
    }

    // ---------------- GAT: 4 heads, f32x2 GEMMs ----------------
    unsigned long long gacc[8][2];
#pragma unroll
    for (int i = 0; i < 8; i++) { gacc[i][0] = 0ull; gacc[i][1] = 0ull; }

    const float* adjb = adj + (size_t)b * 2500;

    for (int h = 0; h < 4; h++) {
        // load W_gat[h] transposed: Wb[c*66 + d]
        for (int i = tid; i < 4096; i += 256) Wb[(i & 63) * 66 + (i >> 6)] = W_gat[h * 4096 + i];
        if (tid < 64)       av[tid] = a_src[h * 64 + tid];
        else if (tid < 128) av[tid] = a_dst[h * 64 + (tid - 64)];
        __syncthreads();

        // GEMM1: WhT[c][n] = sum_d x[n][d] * Wg[d][c]  (output transposed)
        {
            unsigned long long acc[8][2];
#pragma unroll
            for (int i = 0; i < 8; i++) { acc[i][0] = 0ull; acc[i][1] = 0ull; }
#pragma unroll 4
            for (int k = 0; k < 64; k += 2) {
                unsigned long long b0 = ld64(&Wb[tc * 66 + k]);
                unsigned long long b1 = ld64(&Wb[(tc + 32) * 66 + k]);
#pragma unroll
                for (int i = 0; i < 8; i++) {
                    unsigned long long a = ld64(&x[(tn + 8 * i) * 64 + k]);
                    ffma2(acc[i][0], a, b0);
                    ffma2(acc[i][1], a, b1);
                }
            }
#pragma unroll
            for (int i = 0; i < 8; i++) {
                int n = tn + 8 * i;
                WhT[tc * 66 + n]        = hsum2(acc[i][0]);
                WhT[(tc + 32) * 66 + n] = hsum2(acc[i][1]);
            }
        }
        __syncthreads();

        // es/ed from WhT columns
        for (int r = w; r < 50; r += 8) {
            float v  = WhT[lane * 66 + r] * av[lane]      + WhT[(lane + 32) * 66 + r] * av[lane + 32];
            float u2 = WhT[lane * 66 + r] * av[64 + lane] + WhT[(lane + 32) * 66 + r] * av[96 + lane];
            v  = warp_sum(v);
            u2 = warp_sum(u2);
            if (lane == 0) { esd[r] = v; esd[64 + r] = u2; }
        }
        __syncthreads();

        // masked leaky-relu softmax rows
        for (int r = w; r < 50; r += 8) {
            float esr = esd[r];
            float v1 = esr + esd[64 + lane];
            v1 = v1 > 0.f ? v1 : 0.2f * v1;
            v1 = (adjb[r * 50 + lane] > 0.f) ? v1 : -1e9f;
            float v2 = -FLT_MAX;
            if (lane < 18) {
                float t2 = esr + esd[64 + lane + 32];
                t2 = t2 > 0.f ? t2 : 0.2f * t2;
                v2 = (adjb[r * 50 + lane + 32] > 0.f) ? t2 : -1e9f;
            }
            float mx = warp_max(fmaxf(v1, v2));
            float e1 = expf(v1 - mx);
            float e2 = (lane < 18) ? expf(v2 - mx) : 0.f;
            float ssum = warp_sum(e1 + e2);
            float inv = 1.f / ssum;
            attn[r * 64 + lane] = e1 * inv;
            if (lane < 18) attn[r * 64 + lane + 32] = e2 * inv;
        }
        __syncthreads();

        // GEMM2: P[n][c] = sum_m attn[n][m] * Wh[m][c]  (B = WhT, already transposed)
        {
            unsigned long long acc[8][2];
#pragma unroll
            for (int i = 0; i < 8; i++) { acc[i][0] = 0ull; acc[i][1] = 0ull; }
#pragma unroll 5
            for (int k = 0; k < 50; k += 2) {
                unsigned long long b0 = ld64(&WhT[tc * 66 + k]);
                unsigned long long b1 = ld64(&WhT[(tc + 32) * 66 + k]);
#pragma unroll
                for (int i = 0; i < 8; i++) {
                    unsigned long long a = ld64(&attn[(tn + 8 * i) * 64 + k]);
                    ffma2(acc[i][0], a, b0);
                    ffma2(acc[i][1], a, b1);
                }
            }
#pragma unroll
            for (int i = 0; i < 8; i++) {
                int n = tn + 8 * i;
                P[n * 64 + tc]      = hsum2(acc[i][0]);
                P[n * 64 + tc + 32] = hsum2(acc[i][1]);
            }
        }
        __syncthreads();

        // load W_o slice transposed: Wb[c*66 + k]
        for (int i = tid; i < 4096; i += 256) Wb[(i & 63) * 66 + (i >> 6)] = W_o[h * 4096 + i];
        __syncthreads();

        // GEMM3 (accumulating): gacc += P @ W_o[h]
#pragma unroll 4
        for (int k = 0; k < 64; k += 2) {
            unsigned long long b0 = ld64(&Wb[tc * 66 + k]);
            unsigned long long b1 = ld64(&Wb[(tc + 32) * 66 + k]);
#pragma unroll
            for (int i = 0; i < 8; i++) {
                unsigned long long a = ld64(&P[(tn + 8 * i) * 64 + k]);
                ffma2(gacc[i][0], a, b0);
                ffma2(gacc[i][1], a, b1);
            }
        }
        __syncthreads();
    }

    // xI = elu(gacc) row-major in attn; transposed (stride 65) over P (+spill into Wb)
    float* xI  = attn;
    float* xIT = P;
#pragma unroll
    for (int i = 0; i < 8; i++) {
        int n = tn + 8 * i;
        float v0 = hsum2(gacc[i][0]);
        float v1 = hsum2(gacc[i][1]);
        v0 = v0 > 0.f ? v0 : expm1f(v0);
        v1 = v1 > 0.f ? v1 : expm1f(v1);
        xI[n * 64 + tc]         = v0;
        xI[n * 64 + tc + 32]    = v1;
        xIT[tc * 65 + n]        = v0;
        xIT[(tc + 32) * 65 + n] = v1;
    }
    __syncthreads();

    if (tid < 64) {
        float s = 0.f;
        for (int n = 0; n < 50; n++) s += xI[n * 64 + tid];
        uIm[tid] = s * 0.02f;
    }
    __syncthreads();

    // ---------------- aggregates ----------------
    if (w < 5) {
        int c = w;
        float d1 = 0.f, d2 = 0.f;
        for (int d = 0; d < 64; d++) {
            float cv = cand[c * 64 + d];
            d1 += xIT[d * 65 + lane] * cv;
            d2 += xIT[d * 65 + lane + 32] * cv;
        }
        float v1 = d1;
        float v2 = (lane < 18) ? d2 : -FLT_MAX;
        float mx = warp_max(fmaxf(v1, v2));
        float e1 = expf(v1 - mx);
        float e2 = (lane < 18) ? expf(v2 - mx) : 0.f;
        float inv = 1.f / warp_sum(e1 + e2);
        aggw[c * 64 + lane] = e1 * inv;
        if (lane < 18) aggw[c * 64 + lane + 32] = e2 * inv;
        __syncwarp();
        float o1 = 0.f, o2 = 0.f;
        for (int n = 0; n < 50; n++) {
            float wn = aggw[c * 64 + n];
            o1 += wn * xI[n * 64 + lane];
            o2 += wn * xI[n * 64 + lane + 32];
        }
        uIo[c * 64 + lane]      = o1;
        uIo[c * 64 + lane + 32] = o2;
    } else {
        for (int c = w - 5; c < 5; c += 3) {
            float d1 = 0.f;
            if (lane < 10) {
                for (int d = 0; d < 64; d++) d1 += xpT[d * 12 + lane] * cand[c * 64 + d];
            }
            float v1 = (lane < 10) ? d1 : -FLT_MAX;
            float mx = warp_max(v1);
            float e1 = (lane < 10) ? expf(v1 - mx) : 0.f;
            float inv = 1.f / warp_sum(e1);
            if (lane < 10) aggwF[c * 64 + lane] = e1 * inv;
            __syncwarp();
            float o1 = 0.f, o2 = 0.f;
#pragma unroll
            for (int n = 0; n < 10; n++) {
                float wn = aggwF[c * 64 + n];
                o1 += wn * xp[n * 64 + lane];
                o2 += wn * xp[n * 64 + lane + 32];
            }
            uFo[c * 64 + lane]      = o1;
            uFo[c * 64 + lane + 32] = o2;
            __syncwarp();
        }
    }
    __syncthreads();

    // ---------------- u = concat(uF,uI) @ W_pred ----------------
    for (int i = tid; i < 320; i += 256) {
        int c = i >> 6, d = i & 63;
        float acc = 0.f;
#pragma unroll 4
        for (int k = 0; k < 64; k++) acc += uFo[c * 64 + k] * W_pred[k * 64 + d];
#pragma unroll 4
        for (int k = 0; k < 64; k++) acc += uIo[c * 64 + k] * W_pred[(64 + k) * 64 + d];
        uo[i] = acc;
    }
    __syncthreads();

    // ---------------- scores, sI, sF, norms ----------------
    if (tid < 5) {
        float a = 0.f;
        for (int d = 0; d < 64; d++) a += uo[tid * 64 + d] * cand[tid * 64 + d];
        sc5[tid] = a;
    } else if (tid >= 8 && tid < 13) {
        int c = tid - 8; float a = 0.f;
        for (int d = 0; d < 64; d++) a += cand[c * 64 + d] * uIm[d];
        sc5[5 + c] = a;
    } else if (tid >= 16 && tid < 21) {
        int c = tid - 16; float a = 0.f;
        for (int d = 0; d < 64; d++) a += cand[c * 64 + d] * uFm[d];
        sc5[10 + c] = a;
    } else if (tid >= 24 && tid < 29) {
        int c = tid - 24; float a = 0.f;
        for (int d = 0; d < 64; d++) a += cand[c * 64 + d] * cand[c * 64 + d];
        sc5[16 + c] = sqrtf(a);
    } else if (tid == 29) {
        float a = 0.f;
        for (int d = 0; d < 64; d++) a += uIm[d] * uIm[d];
        sc5[21] = sqrtf(a);
    } else if (tid == 30) {
        float a = 0.f;
        for (int d = 0; d < 64; d++) a += uFm[d] * uFm[d];
        sc5[22] = sqrtf(a);
    }
    __syncthreads();

    // ---------------- thread 0: losses ----------------
    if (tid == 0) {
        float p = sc5[0];
        float l1 = 0.f;
        for (int c = 1; c < 5; c++) {
            float z = sc5[c] - p;
            l1 += fmaxf(z, 0.f) + log1pf(expf(-fabsf(z)));
        }
        float vI[5], vF[5]; int iI[5], iF[5];
        for (int j = 0; j < 5; j++) { vI[j] = sc5[5 + j]; iI[j] = j; vF[j] = sc5[10 + j]; iF[j] = j; }
        for (int a2 = 0; a2 < 4; a2++) {
            int m = a2;
            for (int j = a2 + 1; j < 5; j++) if (vI[j] > vI[m]) m = j;
            float tv = vI[a2]; vI[a2] = vI[m]; vI[m] = tv;
            int ti = iI[a2]; iI[a2] = iI[m]; iI[m] = ti;
            m = a2;
            for (int j = a2 + 1; j < 5; j++) if (vF[j] > vF[m]) m = j;
            tv = vF[a2]; vF[a2] = vF[m]; vF[m] = tv;
            ti = iF[a2]; iF[a2] = iF[m]; iF[m] = ti;
        }
        float nuI = sc5[21], nuF = sc5[22];
        float psI = expf(2.f * sc5[5 + iF[0]] / (sc5[16 + iF[0]] * nuI))
                  + expf(2.f * sc5[5 + iF[1]] / (sc5[16 + iF[1]] * nuI));
        float nsI = expf(2.f * sc5[5 + iF[2]] / (sc5[16 + iF[2]] * nuI))
                  + expf(2.f * sc5[5 + iF[3]] / (sc5[16 + iF[3]] * nuI));
        float termI = logf(psI + nsI) - logf(psI);
        float psF = expf(2.f * sc5[10 + iI[0]] / (sc5[16 + iI[0]] * nuF))
                  + expf(2.f * sc5[10 + iI[1]] / (sc5[16 + iI[1]] * nuF));
        float nsF = expf(2.f * sc5[10 + iI[2]] / (sc5[16 + iI[2]] * nuF))
                  + expf(2.f * sc5[10 + iI[3]] / (sc5[16 + iI[3]] * nuF));
        float termF = logf(psF + nsF) - logf(psF);
        g_part[b * 4 + 0] = l1;
        g_part[b * 4 + 3] = termI + termF;
    }

    // ---------------- block reductions ----------------
    red[tid] = regp;
    __syncthreads();
    for (int s2 = 128; s2 > 0; s2 >>= 1) {
        if (tid < s2) red[tid] += red[tid + s2];
        __syncthreads();
    }
    if (tid == 0) g_part[b * 4 + 1] = red[0];
    __syncthreads();
    red[tid] = (tid < 50) ? entp : 0.f;
    __syncthreads();
    for (int s2 = 128; s2 > 0; s2 >>= 1) {
        if (tid < s2) red[tid] += red[tid + s2];
        __syncthreads();
    }
    if (tid == 0) g_part[b * 4 + 2] = red[0];
}

// ---------------------------------------------------------------------------
__global__ void reduce_kernel(const float* __restrict__ W_pred,
                              const float* __restrict__ W_PE,
                              float* __restrict__ out) {
    __shared__ double rs[256];
    int tid = threadIdx.x;
    double a0 = 0, a1 = 0, a2 = 0, a3 = 0, wv = 0;
    for (int i = tid; i < BB; i += 256) {
        const float* p = &g_part[i * 4];
        a0 += p[0]; a1 += p[1]; a2 += p[2]; a3 += p[3];
    }
    for (int i = tid; i < 8192; i += 256) { double v = W_pred[i]; wv += v * v; }
    for (int i = tid; i < 4096; i += 256) { double v = W_PE[i];   wv += v * v; }
    double vals[5] = {a0, a1, a2, a3, wv};
    double res[5];
    for (int j = 0; j < 5; j++) {
        rs[tid] = vals[j];
        __syncthreads();
        for (int s = 128; s > 0; s >>= 1) {
            if (tid < s) rs[tid] += rs[tid + s];
            __syncthreads();
        }
        res[j] = rs[0];
        __syncthreads();
    }
    if (tid == 0) {
        out[0] = (float)(res[0] / (4096.0 * 4.0));
        out[1] = (float)(res[1] / 4096.0 + res[4]);
        out[2] = (float)(res[2] / (50.0 * 4096.0));
        out[3] = (float)(res[3] / 4096.0);
    }
}

// ---------------------------------------------------------------------------
extern "C" void kernel_launch(void* const* d_in, const int* in_sizes, int n_in,
                              void* d_out, int out_size) {
    const float* emb      = (const float*)d_in[0];
    const float* W_PE     = (const float*)d_in[1];
    const float* W_pred   = (const float*)d_in[2];
    const float* W_gat    = (const float*)d_in[3];
    const float* a_src    = (const float*)d_in[4];
    const float* a_dst    = (const float*)d_in[5];
    const float* W_o      = (const float*)d_in[6];
    const float* W_assign = (const float*)d_in[7];
    const float* adj      = (const float*)d_in[8];
    const int*   history  = (const int*)d_in[9];
    const int*   timestp  = (const int*)d_in[10];
    const int*   pos_id   = (const int*)d_in[11];
    const int*   neg_id   = (const int*)d_in[12];
    const int*   stp      = (const int*)d_in[13];
    float* out = (float*)d_out;

    const int smem_bytes = 25376 * 4;  // 101504
    cudaFuncSetAttribute(main_kernel, cudaFuncAttributeMaxDynamicSharedMemorySize, smem_bytes);

    pew_kernel<<<MAXLEN, 64>>>(W_PE);
    main_kernel<<<BB, 256, smem_bytes>>>(emb, W_pred, W_gat, a_src, a_dst, W_o,
                                         W_assign, adj, history, timestp,
                                         pos_id, neg_id, stp);
    reduce_kernel<<<1, 256>>>(W_pred, W_PE, out);
}